// round 16
// baseline (speedup 1.0000x reference)
#include <cuda_runtime.h>
#include <cuda_bf16.h>
#include <cstdint>
#include <math.h>

#define NN 50000
#define NE 800000
#define DD 128
#define NG 16

#define NEG_INF_BITS 0xFF800000u

#define SCAN_B 256
#define NBLK ((NN + SCAN_B - 1) / SCAN_B)   // 196
#define NTILES ((NN + 127) / 128)           // 391
#define GEMM_GRID 148

// ---------------- scratch (no cudaMalloc). uint4/float4 for 16B alignment ----------------
__device__ float4 g_bufA4[NN * DD / 4];       // fp32 h ping
__device__ float4 g_bufB4[NN * DD / 4];       // fp32 h pong
__device__ uint4  g_Ahi4[NN * 256 * 2 / 16];  // bf16 hi of [h | agg], [NN][256]
__device__ uint4  g_Alo4[NN * 256 * 2 / 16];  // bf16 lo
__device__ uint4  g_Bhi4[4 * 128 * 256 * 2 / 16]; // Wt hi per step, [4][128 n][256 k]
__device__ uint4  g_Blo4[4 * 128 * 256 * 2 / 16];
__device__ float g_xg[NG * DD];
__device__ int g_i64;
// CSR (dst-sorted adjacency)
__device__ int g_deg[NN];
__device__ int g_off[NN + 1];
__device__ int g_cur[NN];
__device__ int g_csr[NE];
__device__ int g_part[NBLK];
__device__ int g_poff[NBLK];

__device__ __forceinline__ const float* sel_in(int sel, const float* x, const float* dout) {
    return sel == 0 ? x : sel == 1 ? (const float*)g_bufA4 : sel == 2 ? (const float*)g_bufB4 : dout;
}
__device__ __forceinline__ float* sel_out(int sel, float* dout) {
    return sel == 1 ? (float*)g_bufA4 : sel == 2 ? (float*)g_bufB4 : dout;
}

__device__ __forceinline__ void atomicMaxF(float* a, float v) {
    if (v >= 0.f) atomicMax((int*)a, __float_as_int(v));
    else          atomicMin((unsigned int*)a, __float_as_uint(v));
}

__device__ __forceinline__ float fixneg(float v) {
    return (__float_as_uint(v) == NEG_INF_BITS) ? 0.f : v;
}

__device__ __forceinline__ unsigned pack_bf2(__nv_bfloat16 a, __nv_bfloat16 b) {
    __nv_bfloat162 t(a, b);
    return *(unsigned*)&t;
}
__device__ __forceinline__ void split_bf16(float v, __nv_bfloat16& hi, __nv_bfloat16& lo) {
    hi = __float2bfloat16(v);
    lo = __float2bfloat16(v - __bfloat162float(hi));
}

// ---------------- PTX helpers (tcgen05 / mbarrier) ----------------
__device__ __forceinline__ uint32_t smem_u32(const void* p) {
    uint32_t a;
    asm("{ .reg .u64 t; cvta.to.shared.u64 t, %1; cvt.u32.u64 %0, t; }" : "=r"(a) : "l"(p));
    return a;
}
#define MBAR_INIT(a, c) asm volatile("mbarrier.init.shared.b64 [%0], %1;" :: "r"(a), "r"(c) : "memory")
#define MBAR_INVAL(a)   asm volatile("mbarrier.inval.shared.b64 [%0];" :: "r"(a) : "memory")
#define MBAR_WAIT(a, ph) do { \
    uint32_t _m = (a), _p = (ph), _d; \
    asm volatile("{ .reg .pred p; mbarrier.try_wait.parity.acquire.cta.shared::cta.b64 p, [%1], %2; selp.b32 %0, 1, 0, p; }" \
        : "=r"(_d) : "r"(_m), "r"(_p) : "memory"); \
    if (!_d) { \
        asm volatile("{ .reg .pred P1; WL%=: mbarrier.try_wait.parity.acquire.cta.shared::cta.b64 P1, [%0], %1, 0x989680; @P1 bra.uni WD%=; bra.uni WL%=; WD%=: }" \
            :: "r"(_m), "r"(_p) : "memory"); \
    } } while (0)

#if defined(__CUDA_ARCH_FEAT_SM103_ALL)
__device__ __forceinline__ uint32_t elect_one() {
    uint32_t p;
    asm volatile("{ .reg .pred p; elect.sync _|p, 0xFFFFFFFF; selp.b32 %0, 1, 0, p; }" : "=r"(p));
    return p;
}
#define TC_ALLOC(sa, n)  asm volatile("tcgen05.alloc.cta_group::1.sync.aligned.shared::cta.b32 [%0], %1;" :: "r"(sa), "r"(n) : "memory")
#define TC_DEALLOC(t, n) asm volatile("tcgen05.dealloc.cta_group::1.sync.aligned.b32 %0, %1;" :: "r"(t), "r"(n))
#define TC_COMMIT(a)     asm volatile("tcgen05.commit.cta_group::1.mbarrier::arrive::one.shared::cluster.b64 [%0];" :: "r"(a) : "memory")
#define TC_FENCE_AFTER() asm volatile("tcgen05.fence::after_thread_sync;" ::: "memory")
#define TC_FENCE_BEFORE() asm volatile("tcgen05.fence::before_thread_sync;" ::: "memory")
#define TC_WAIT_LD()     asm volatile("tcgen05.wait::ld.sync.aligned;" ::: "memory")
#define FENCE_ASYNC()    asm volatile("fence.proxy.async.shared::cta;" ::: "memory")

#define TC_LD_X32(r, ta) \
    asm volatile("tcgen05.ld.sync.aligned.32x32b.x32.b32 " \
        "{%0,%1,%2,%3,%4,%5,%6,%7,%8,%9,%10,%11,%12,%13,%14,%15," \
        "%16,%17,%18,%19,%20,%21,%22,%23,%24,%25,%26,%27,%28,%29,%30,%31}, [%32];" \
        : "=r"((r)[0]),"=r"((r)[1]),"=r"((r)[2]),"=r"((r)[3]),"=r"((r)[4]),"=r"((r)[5]),"=r"((r)[6]),"=r"((r)[7]), \
          "=r"((r)[8]),"=r"((r)[9]),"=r"((r)[10]),"=r"((r)[11]),"=r"((r)[12]),"=r"((r)[13]),"=r"((r)[14]),"=r"((r)[15]), \
          "=r"((r)[16]),"=r"((r)[17]),"=r"((r)[18]),"=r"((r)[19]),"=r"((r)[20]),"=r"((r)[21]),"=r"((r)[22]),"=r"((r)[23]), \
          "=r"((r)[24]),"=r"((r)[25]),"=r"((r)[26]),"=r"((r)[27]),"=r"((r)[28]),"=r"((r)[29]),"=r"((r)[30]),"=r"((r)[31]) \
        : "r"(ta))

// SMEM descriptor: SW128, version=1 (Blackwell), SBO=64, LBO=1 (canonical K-major 128B rows)
static __device__ __forceinline__ uint64_t make_desc(uint32_t addr) {
    const uint64_t base = (uint64_t(2) << 61) | (uint64_t(1) << 46) | (uint64_t(64) << 32) | (uint64_t(1) << 16);
    return base | ((uint64_t)(addr >> 4) & 0x3FFF);
}

// cg1 SS bf16 MMA: D[M=128,N=128] fp32 += A[128,16] * B[128,16]^T
#define GEMM_IDESC 0x08200490u
__device__ __forceinline__ void mma_f16_ss(uint32_t d, uint64_t ad, uint64_t bd, uint32_t en) {
    asm volatile(
        "{ .reg .pred p; setp.ne.u32 p, %5, 0;\n\t"
        "tcgen05.mma.cta_group::1.kind::f16 [%0], %1, %2, %3, {%4, %4, %4, %4}, p; }"
        :: "r"(d), "l"(ad), "l"(bd), "r"(GEMM_IDESC), "r"(0u), "r"(en)
        : "memory");
}
#endif  // __CUDA_ARCH_FEAT_SM103_ALL

// canonical SW128 byte offset within a 128row x 128byte tile
__device__ __forceinline__ uint32_t tile_off(int row, int i16 /*16B chunk 0..7*/) {
    uint32_t byte = (uint32_t)row * 128u + (uint32_t)i16 * 16u;
    return byte ^ ((byte >> 3) & 0x70);
}

// ---------------- dtype detection ----------------
__global__ void k_detect(const int* __restrict__ ei32) {
    int mode = 1;
    for (int i = 0; i < 64; ++i) {
        if (ei32[2 * i + 1] != 0) { mode = 0; break; }
    }
    g_i64 = mode;
}

__device__ __forceinline__ int idx_at(const int* p32, int i) {
    return g_i64 ? p32[2 * i] : p32[i];
}

// ---------------- CSR build ----------------
__global__ void k_zero_deg() {
    int i = blockIdx.x * blockDim.x + threadIdx.x;
    if (i < NN) g_deg[i] = 0;
}

__global__ void k_count(const int* __restrict__ ei32) {
    int e = blockIdx.x * blockDim.x + threadIdx.x;
    if (e < NE) atomicAdd(&g_deg[idx_at(ei32, NE + e)], 1);
}

__global__ void k_partial() {
    __shared__ int sh[SCAN_B];
    int idx = blockIdx.x * SCAN_B + threadIdx.x;
    int v = (idx < NN) ? g_deg[idx] : 0;
    sh[threadIdx.x] = v;
    __syncthreads();
    for (int off = SCAN_B / 2; off > 0; off >>= 1) {
        if (threadIdx.x < off) sh[threadIdx.x] += sh[threadIdx.x + off];
        __syncthreads();
    }
    if (threadIdx.x == 0) g_part[blockIdx.x] = sh[0];
}

__global__ void k_scanpart() {
    __shared__ int sh[SCAN_B];
    int t = threadIdx.x;
    int v = (t < NBLK) ? g_part[t] : 0;
    sh[t] = v;
    __syncthreads();
    for (int off = 1; off < SCAN_B; off <<= 1) {
        int u = (t >= off) ? sh[t - off] : 0;
        __syncthreads();
        sh[t] += u;
        __syncthreads();
    }
    if (t < NBLK) g_poff[t] = sh[t] - v;
}

__global__ void k_offsets() {
    __shared__ int sh[SCAN_B];
    int t = threadIdx.x;
    int idx = blockIdx.x * SCAN_B + t;
    int d = (idx < NN) ? g_deg[idx] : 0;
    sh[t] = d;
    __syncthreads();
    for (int off = 1; off < SCAN_B; off <<= 1) {
        int u = (t >= off) ? sh[t - off] : 0;
        __syncthreads();
        sh[t] += u;
        __syncthreads();
    }
    if (idx < NN) {
        int o = g_poff[blockIdx.x] + sh[t] - d;
        g_off[idx] = o;
        g_cur[idx] = o;
        if (idx == NN - 1) g_off[NN] = o + d;
    }
}

__global__ void k_fill(const int* __restrict__ ei32) {
    int e = blockIdx.x * blockDim.x + threadIdx.x;
    if (e < NE) {
        int d = idx_at(ei32, NE + e);
        int s = idx_at(ei32, e);
        int pos = atomicAdd(&g_cur[d], 1);
        g_csr[pos] = s;
    }
}

// ---------------- weight prep: Wt hi/lo [4][128 n][256 k] ----------------
__global__ void k_wprep(const float* __restrict__ w0, const float* __restrict__ w1,
                        const float* __restrict__ w2, const float* __restrict__ w3) {
    int idx = blockIdx.x * blockDim.x + threadIdx.x;
    if (idx >= 4 * 128 * 256) return;
    int s = idx >> 15;
    int rem = idx & 32767;
    int n = rem >> 8;
    int k = rem & 255;
    const float* w = s == 0 ? w0 : s == 1 ? w1 : s == 2 ? w2 : w3;
    float v = w[(size_t)k * 128 + n];
    __nv_bfloat16 hi, lo;
    split_bf16(v, hi, lo);
    ((__nv_bfloat16*)g_Bhi4)[idx] = hi;
    ((__nv_bfloat16*)g_Blo4)[idx] = lo;
}

// ---------------- x -> A hi/lo (cols 0..127) ----------------
__global__ void k_conv0(const float* __restrict__ x) {
    int idx = blockIdx.x * blockDim.x + threadIdx.x;  // NN*32
    if (idx >= NN * 32) return;
    int gr = idx >> 5;
    int cg = (idx & 31) * 4;
    float4 v = *(const float4*)(x + (size_t)gr * DD + cg);
    __nv_bfloat16 h0, h1, h2, h3, l0, l1, l2, l3;
    split_bf16(v.x, h0, l0); split_bf16(v.y, h1, l1);
    split_bf16(v.z, h2, l2); split_bf16(v.w, h3, l3);
    unsigned* hp = (unsigned*)g_Ahi4 + (size_t)gr * 128 + cg / 2;
    unsigned* lp = (unsigned*)g_Alo4 + (size_t)gr * 128 + cg / 2;
    hp[0] = pack_bf2(h0, h1); hp[1] = pack_bf2(h2, h3);
    lp[0] = pack_bf2(l0, l1); lp[1] = pack_bf2(l2, l3);
}

// ---------------- aggregation: warp-per-node gather-max -> A hi/lo cols 128..255 ----------------
__global__ void k_agg(int insel, const float* __restrict__ x, const float* __restrict__ doutc) {
    const float* h = sel_in(insel, x, doutc);
    const int warp = (blockIdx.x * blockDim.x + threadIdx.x) >> 5;
    const int lane = threadIdx.x & 31;
    if (warp >= NN) return;
    const int e0 = g_off[warp];
    const int e1 = g_off[warp + 1];
    float4 m = make_float4(0.f, 0.f, 0.f, 0.f);
    if (e1 > e0) {
        const float ni = __uint_as_float(NEG_INF_BITS);
        m = make_float4(ni, ni, ni, ni);
        int e = e0;
        for (; e + 3 < e1; e += 4) {
            int s0 = g_csr[e], s1 = g_csr[e + 1], s2 = g_csr[e + 2], s3 = g_csr[e + 3];
            float4 v0 = ((const float4*)h)[(size_t)s0 * 32 + lane];
            float4 v1 = ((const float4*)h)[(size_t)s1 * 32 + lane];
            float4 v2 = ((const float4*)h)[(size_t)s2 * 32 + lane];
            float4 v3 = ((const float4*)h)[(size_t)s3 * 32 + lane];
            m.x = fmaxf(fmaxf(m.x, v0.x), fmaxf(v1.x, fmaxf(v2.x, v3.x)));
            m.y = fmaxf(fmaxf(m.y, v0.y), fmaxf(v1.y, fmaxf(v2.y, v3.y)));
            m.z = fmaxf(fmaxf(m.z, v0.z), fmaxf(v1.z, fmaxf(v2.z, v3.z)));
            m.w = fmaxf(fmaxf(m.w, v0.w), fmaxf(v1.w, fmaxf(v2.w, v3.w)));
        }
        for (; e < e1; ++e) {
            int s0 = g_csr[e];
            float4 v0 = ((const float4*)h)[(size_t)s0 * 32 + lane];
            m.x = fmaxf(m.x, v0.x); m.y = fmaxf(m.y, v0.y);
            m.z = fmaxf(m.z, v0.z); m.w = fmaxf(m.w, v0.w);
        }
    }
    __nv_bfloat16 h0, h1, h2, h3, l0, l1, l2, l3;
    split_bf16(m.x, h0, l0); split_bf16(m.y, h1, l1);
    split_bf16(m.z, h2, l2); split_bf16(m.w, h3, l3);
    unsigned* hp = (unsigned*)g_Ahi4 + (size_t)warp * 128 + 64 + lane * 2;
    unsigned* lp = (unsigned*)g_Alo4 + (size_t)warp * 128 + 64 + lane * 2;
    hp[0] = pack_bf2(h0, h1); hp[1] = pack_bf2(h2, h3);
    lp[0] = pack_bf2(l0, l1); lp[1] = pack_bf2(l2, l3);
}

// ---------------- persistent tcgen05 GEMM, resident B, 3-deep A pipeline, D ping-pong ----------------
#define S_TMEM 0
#define S_MBAR 8              // 3 mbars: 8, 16, 24
#define S_BIAS 64
#define S_A 1024
#define A_SET_BYTES 32768     // Ahi 16KB + Alo 16KB
#define A_T_ALO 16384
#define S_B (S_A + 3 * A_SET_BYTES)        // 99328
#define B_CHUNK_BYTES 32768   // Bhi 16KB + Blo 16KB
#define B_T_BLO 16384
#define S_TOTAL (S_B + 4 * B_CHUNK_BYTES)  // 230400 (<= 227KB limit)

__global__ void __launch_bounds__(256)
k_gemm_tc(int insel, int outsel, const float* __restrict__ x, float* __restrict__ dout,
          int step, const float* __restrict__ b, int addskip, int writeconv) {
    extern __shared__ char smem[];
    const float* h = sel_in(insel, x, dout);
    float* out = sel_out(outsel, dout);
    const int tid = threadIdx.x;
    const int wid = tid >> 5;
    const int lane = tid & 31;

#if defined(__CUDA_ARCH_FEAT_SM103_ALL)
    const uint32_t sb = smem_u32(smem);
    if (wid == 0) TC_ALLOC(sb + S_TMEM, 256);
    if (tid == 0) {
        MBAR_INIT(sb + S_MBAR + 0, 1);
        MBAR_INIT(sb + S_MBAR + 8, 1);
        MBAR_INIT(sb + S_MBAR + 16, 1);
    }
    if (tid < 32) ((float4*)(smem + S_BIAS))[tid] = ((const float4*)b)[tid];
    __syncthreads();
    uint32_t tmem;
    asm volatile("ld.shared.b32 %0, [%1];" : "=r"(tmem) : "r"(sb + S_TMEM));

    const size_t boff = (size_t)step * 4096;  // uint4 stride per step
    const int lrow = tid >> 1;
    const int lhalf = (tid & 1) * 4;   // i16 base 0 or 4

    // ---- load B (all 4 chunks, hi+lo) once into resident smem ----
    {
#pragma unroll
        for (int c = 0; c < 4; ++c) {
            const uint4* bh = g_Bhi4 + boff + (size_t)lrow * 32 + (size_t)c * 8 + lhalf;
            const uint4* bl = g_Blo4 + boff + (size_t)lrow * 32 + (size_t)c * 8 + lhalf;
            char* base = smem + S_B + c * B_CHUNK_BYTES;
#pragma unroll
            for (int i = 0; i < 4; ++i) {
                uint32_t so = tile_off(lrow, lhalf + i);
                *(uint4*)(base + so) = bh[i];
                *(uint4*)(base + B_T_BLO + so) = bl[i];
            }
        }
        FENCE_ASYNC();
        __syncthreads();
    }

    auto load_chunk = [&](int m0, int c, int set) {
        const uint4 z4 = make_uint4(0, 0, 0, 0);
        const int gr = m0 + lrow;
        const bool valid = gr < NN;
        const uint4* ah = g_Ahi4 + (size_t)gr * 32 + (size_t)c * 8 + lhalf;
        const uint4* al = g_Alo4 + (size_t)gr * 32 + (size_t)c * 8 + lhalf;
        char* base = smem + S_A + set * A_SET_BYTES;
#pragma unroll
        for (int i = 0; i < 4; ++i) {
            uint32_t so = tile_off(lrow, lhalf + i);
            *(uint4*)(base + so) = valid ? ah[i] : z4;
            *(uint4*)(base + A_T_ALO + so) = valid ? al[i] : z4;
        }
    };

    auto issue_chunk = [&](uint32_t dtm, int c, int set) {
        if (wid == 0 && elect_one()) {
            uint32_t abuf = sb + S_A + set * A_SET_BYTES;
            uint32_t bbuf = sb + S_B + c * B_CHUNK_BYTES;
            uint64_t dah = make_desc(abuf);
            uint64_t dal = make_desc(abuf + A_T_ALO);
            uint64_t dbh = make_desc(bbuf);
            uint64_t dbl = make_desc(bbuf + B_T_BLO);
#pragma unroll
            for (int ks = 0; ks < 4; ++ks) {
                uint64_t off = (uint64_t)(ks * 2);
                mma_f16_ss(dtm, dah + off, dbh + off, (c == 0 && ks == 0) ? 0u : 1u);
            }
#pragma unroll
            for (int ks = 0; ks < 4; ++ks) {
                uint64_t off = (uint64_t)(ks * 2);
                mma_f16_ss(dtm, dah + off, dbl + off, 1u);
            }
#pragma unroll
            for (int ks = 0; ks < 4; ++ks) {
                uint64_t off = (uint64_t)(ks * 2);
                mma_f16_ss(dtm, dal + off, dbh + off, 1u);
            }
            TC_COMMIT(sb + S_MBAR + set * 8);
        }
    };

    const float* bias = (const float*)(smem + S_BIAS);
    auto epilogue = [&](int m0, uint32_t dtm) {
        const int egr = m0 + (wid & 3) * 32 + lane;
        const int colbase = (wid >> 2) * 64;
        uint32_t r[64];
        TC_LD_X32(r, dtm + colbase);
        TC_LD_X32(r + 32, dtm + colbase + 32);
        TC_WAIT_LD();
        if (egr < NN) {
#pragma unroll
            for (int cq = 0; cq < 64; cq += 32) {
                const int cb = colbase + cq;
                const uint32_t* rr = r + cq;
                const float* hr = h + (size_t)egr * DD + cb;
                float* orow = out + (size_t)egr * DD + cb;
                unsigned* hp = (unsigned*)g_Ahi4 + (size_t)egr * 128 + cb / 2;
                unsigned* lp = (unsigned*)g_Alo4 + (size_t)egr * 128 + cb / 2;
#pragma unroll
                for (int c0 = 0; c0 < 32; c0 += 4) {
                    float4 v;
                    v.x = __uint_as_float(rr[c0 + 0]) + bias[cb + c0 + 0];
                    v.y = __uint_as_float(rr[c0 + 1]) + bias[cb + c0 + 1];
                    v.z = __uint_as_float(rr[c0 + 2]) + bias[cb + c0 + 2];
                    v.w = __uint_as_float(rr[c0 + 3]) + bias[cb + c0 + 3];
                    v.x = v.x > 0.f ? v.x : 0.01f * v.x;
                    v.y = v.y > 0.f ? v.y : 0.01f * v.y;
                    v.z = v.z > 0.f ? v.z : 0.01f * v.z;
                    v.w = v.w > 0.f ? v.w : 0.01f * v.w;
                    if (addskip) {
                        float4 hv = *(const float4*)(hr + c0);
                        v.x += hv.x; v.y += hv.y; v.z += hv.z; v.w += hv.w;
                    }
                    *(float4*)(orow + c0) = v;
                    if (writeconv) {
                        __nv_bfloat16 h0, h1, h2, h3, l0, l1, l2, l3;
                        split_bf16(v.x, h0, l0); split_bf16(v.y, h1, l1);
                        split_bf16(v.z, h2, l2); split_bf16(v.w, h3, l3);
                        hp[c0 / 2 + 0] = pack_bf2(h0, h1); hp[c0 / 2 + 1] = pack_bf2(h2, h3);
                        lp[c0 / 2 + 0] = pack_bf2(l0, l1); lp[c0 / 2 + 1] = pack_bf2(l2, l3);
                    }
                }
            }
        }
    };

    int use[3] = {0, 0, 0};   // commits issued per set
    int iter = 0;
    int prev_m0 = -1;
    for (int tile = blockIdx.x; tile < NTILES; tile += GEMM_GRID) {
        const int m0 = tile * 128;
        const uint32_t dcur = tmem + (iter & 1) * 128;
        const uint32_t dprev = tmem + ((iter ^ 1) & 1) * 128;

#pragma unroll
        for (int c = 0; c < 4; ++c) {
            const int g = iter * 4 + c;
            const int set = g % 3;
            if (use[set] > 0) { MBAR_WAIT(sb + S_MBAR + set * 8, (use[set] - 1) & 1); }
            __syncthreads();
            load_chunk(m0, c, set);
            FENCE_ASYNC();
            __syncthreads();
            issue_chunk(dcur, c, set);
            use[set]++;
            // after issuing c2 (whose wait covered prev tile's last chunk), drain prev epilogue
            if (c == 2 && iter > 0) {
                TC_FENCE_AFTER();
                epilogue(prev_m0, dprev);
            }
        }

        prev_m0 = m0;
        ++iter;
    }
    if (iter > 0) {
        const int lastset = (iter * 4 - 1) % 3;
        MBAR_WAIT(sb + S_MBAR + lastset * 8, (use[lastset] - 1) & 1);
        TC_FENCE_AFTER();
        __syncthreads();
        epilogue(prev_m0, tmem + ((iter - 1) & 1) * 128);
    }
    TC_FENCE_BEFORE();
    __syncthreads();
    if (wid == 0) {
        if (elect_one()) {
            MBAR_INVAL(sb + S_MBAR + 0);
            MBAR_INVAL(sb + S_MBAR + 8);
            MBAR_INVAL(sb + S_MBAR + 16);
        }
        TC_DEALLOC(tmem, 256);
    }
#else
    // Correct scalar fallback (only used if the generic compute_103 PTX is JIT'd).
    if (tid < 32) ((float4*)(smem + S_BIAS))[tid] = ((const float4*)b)[tid];
    __syncthreads();
    const float* bias = (const float*)(smem + S_BIAS);
    for (int tile = blockIdx.x; tile < NTILES; tile += GEMM_GRID) {
        const int m0 = tile * 128;
        const int egr = m0 + (wid & 3) * 32 + lane;
        const int colbase = (wid >> 2) * 64;
        if (egr < NN) {
            const __nv_bfloat16* ah = (const __nv_bfloat16*)g_Ahi4 + (size_t)egr * 256;
            const __nv_bfloat16* al = (const __nv_bfloat16*)g_Alo4 + (size_t)egr * 256;
            const __nv_bfloat16* BH = (const __nv_bfloat16*)g_Bhi4 + (size_t)step * 128 * 256;
            const __nv_bfloat16* BL = (const __nv_bfloat16*)g_Blo4 + (size_t)step * 128 * 256;
            for (int cq = 0; cq < 64; cq += 4) {
                int cb = colbase + cq;
                float acc[4] = {0.f, 0.f, 0.f, 0.f};
                for (int k = 0; k < 256; ++k) {
                    float ahv = __bfloat162float(ah[k]);
                    float alv = __bfloat162float(al[k]);
#pragma unroll
                    for (int j = 0; j < 4; ++j) {
                        float bh = __bfloat162float(BH[(size_t)(cb + j) * 256 + k]);
                        float bl = __bfloat162float(BL[(size_t)(cb + j) * 256 + k]);
                        acc[j] += ahv * bh + ahv * bl + alv * bh;
                    }
                }
                const float* hr = h + (size_t)egr * DD;
                float* orow = out + (size_t)egr * DD;
                unsigned* hp = (unsigned*)g_Ahi4 + (size_t)egr * 128;
                unsigned* lp = (unsigned*)g_Alo4 + (size_t)egr * 128;
#pragma unroll
                for (int j = 0; j < 4; j += 2) {
                    float v0 = acc[j] + bias[cb + j];
                    float v1 = acc[j + 1] + bias[cb + j + 1];
                    v0 = v0 > 0.f ? v0 : 0.01f * v0;
                    v1 = v1 > 0.f ? v1 : 0.01f * v1;
                    if (addskip) { v0 += hr[cb + j]; v1 += hr[cb + j + 1]; }
                    orow[cb + j] = v0;
                    orow[cb + j + 1] = v1;
                    if (writeconv) {
                        __nv_bfloat16 h0, h1, l0, l1;
                        split_bf16(v0, h0, l0); split_bf16(v1, h1, l1);
                        hp[(cb + j) / 2] = pack_bf2(h0, h1);
                        lp[(cb + j) / 2] = pack_bf2(l0, l1);
                    }
                }
            }
        }
    }
#endif
}

// ---------------- global pool ----------------
__global__ void k_init_xg() {
    unsigned int i = blockIdx.x * blockDim.x + threadIdx.x;
    if (i < NG * DD) ((unsigned int*)g_xg)[i] = NEG_INF_BITS;
}

__device__ __forceinline__ int lower_bound_b(const int* b32, int n, int v) {
    int lo = 0, hi = n;
    while (lo < hi) {
        int mid = (lo + hi) >> 1;
        if (idx_at(b32, mid) < v) lo = mid + 1;
        else hi = mid;
    }
    return lo;
}

__global__ void k_segmax(const float* __restrict__ h, const int* __restrict__ batch32) {
    const int g = blockIdx.x;
    const int chunk = blockIdx.y;
    const int d = threadIdx.x;
    int start = lower_bound_b(batch32, NN, g);
    int end = lower_bound_b(batch32, NN, g + 1);
    int len = end - start;
    if (len <= 0) return;
    int per = (len + gridDim.y - 1) / gridDim.y;
    int s = start + chunk * per;
    int e = s + per;
    if (e > end) e = end;
    if (s >= e) return;
    float m = __uint_as_float(NEG_INF_BITS);
    for (int r = s; r < e; ++r) m = fmaxf(m, h[(size_t)r * DD + d]);
    atomicMaxF(&g_xg[g * DD + d], m);
}

__global__ void k_combine(float* __restrict__ dout, const float* __restrict__ wg,
                          const float* __restrict__ bg, int out_size) {
    const int g = blockIdx.x;
    const int n = threadIdx.x;
    float acc = bg[n];
    for (int k = 0; k < DD; ++k) {
        float xv = fixneg(g_xg[g * DD + k]);
        acc = fmaf(xv, wg[(size_t)k * DD + n], acc);
    }
    acc = acc > 0.f ? acc : 0.01f * acc;
    long long oi = (long long)NN * DD + g * DD + n;
    if (oi < (long long)out_size) dout[oi] = acc;
}

// ---------------- launch ----------------
extern "C" void kernel_launch(void* const* d_in, const int* in_sizes, int n_in,
                              void* d_out, int out_size) {
    const float* x = (const float*)d_in[0];
    const int* ei32 = (const int*)d_in[1];
    const int* batch32 = (const int*)d_in[2];
    const int wb = n_in - 10;  // w0,b0,w1,b1,w2,b2,w3,b3,wg,bg
    float* dout = (float*)d_out;

    static int smem_set = 0;
    if (!smem_set) {
        cudaFuncSetAttribute(k_gemm_tc, cudaFuncAttributeMaxDynamicSharedMemorySize, S_TOTAL);
        smem_set = 1;
    }

    k_detect<<<1, 1>>>(ei32);

    // CSR build
    k_zero_deg<<<(NN + 255) / 256, 256>>>();
    k_count<<<(NE + 255) / 256, 256>>>(ei32);
    k_partial<<<NBLK, SCAN_B>>>();
    k_scanpart<<<1, SCAN_B>>>();
    k_offsets<<<NBLK, SCAN_B>>>();
    k_fill<<<(NE + 255) / 256, 256>>>(ei32);

    // weight + input conversion
    k_wprep<<<(4 * 128 * 256 + 255) / 256, 256>>>(
        (const float*)d_in[wb + 0], (const float*)d_in[wb + 2],
        (const float*)d_in[wb + 4], (const float*)d_in[wb + 6]);
    k_conv0<<<(NN * 32 + 255) / 256, 256>>>(x);

    int insel = 0;
    for (int s = 0; s < 4; ++s) {
        int outsel = (s == 3) ? 3 : ((s % 2 == 0) ? 1 : 2);
        k_agg<<<(NN * 32 + 255) / 256, 256>>>(insel, x, dout);
        k_gemm_tc<<<GEMM_GRID, 256, S_TOTAL>>>(insel, outsel, x, dout, s,
                                               (const float*)d_in[wb + 2 * s + 1],
                                               s > 0 ? 1 : 0, s < 3 ? 1 : 0);
        insel = outsel;
    }

    k_init_xg<<<8, 256>>>();
    dim3 gsg(NG, 32);
    k_segmax<<<gsg, 128>>>(dout, batch32);
    k_combine<<<NG, 128>>>(dout, (const float*)d_in[wb + 8], (const float*)d_in[wb + 9], out_size);
}

// round 17
// speedup vs baseline: 1.0805x; 1.0805x over previous
#include <cuda_runtime.h>
#include <cuda_bf16.h>
#include <cstdint>
#include <math.h>

#define NN 50000
#define NE 800000
#define DD 128
#define NG 16

#define NEG_INF_BITS 0xFF800000u

#define SCAN_B 256
#define NBLK ((NN + SCAN_B - 1) / SCAN_B)   // 196
#define NTILES ((NN + 127) / 128)           // 391
#define GEMM_GRID 148

// ---------------- scratch (no cudaMalloc). uint4/float4 for 16B alignment ----------------
__device__ float4 g_bufA4[NN * DD / 4];       // fp32 h ping
__device__ float4 g_bufB4[NN * DD / 4];       // fp32 h pong
__device__ uint4  g_Ahi4[NN * 256 * 2 / 16];  // bf16 hi of [h | agg], [NN][256]
__device__ uint4  g_Alo4[NN * 256 * 2 / 16];  // bf16 lo
__device__ uint4  g_Bhi4[4 * 128 * 256 * 2 / 16]; // Wt hi per step, [4][128 n][256 k]
__device__ uint4  g_Blo4[4 * 128 * 256 * 2 / 16];
__device__ float g_xg[NG * DD];
__device__ int g_i64;
// CSR (dst-sorted adjacency)
__device__ int g_deg[NN];
__device__ int g_off[NN + 1];
__device__ int g_cur[NN];
__device__ int g_csr[NE];
__device__ int g_part[NBLK];
__device__ int g_poff[NBLK];

__device__ __forceinline__ const float* sel_in(int sel, const float* x, const float* dout) {
    return sel == 0 ? x : sel == 1 ? (const float*)g_bufA4 : sel == 2 ? (const float*)g_bufB4 : dout;
}
__device__ __forceinline__ float* sel_out(int sel, float* dout) {
    return sel == 1 ? (float*)g_bufA4 : sel == 2 ? (float*)g_bufB4 : dout;
}

__device__ __forceinline__ void atomicMaxF(float* a, float v) {
    if (v >= 0.f) atomicMax((int*)a, __float_as_int(v));
    else          atomicMin((unsigned int*)a, __float_as_uint(v));
}

__device__ __forceinline__ float fixneg(float v) {
    return (__float_as_uint(v) == NEG_INF_BITS) ? 0.f : v;
}

__device__ __forceinline__ unsigned pack_bf2(__nv_bfloat16 a, __nv_bfloat16 b) {
    __nv_bfloat162 t(a, b);
    return *(unsigned*)&t;
}
__device__ __forceinline__ void split_bf16(float v, __nv_bfloat16& hi, __nv_bfloat16& lo) {
    hi = __float2bfloat16(v);
    lo = __float2bfloat16(v - __bfloat162float(hi));
}

// ---------------- PTX helpers (tcgen05 / mbarrier) ----------------
__device__ __forceinline__ uint32_t smem_u32(const void* p) {
    uint32_t a;
    asm("{ .reg .u64 t; cvta.to.shared.u64 t, %1; cvt.u32.u64 %0, t; }" : "=r"(a) : "l"(p));
    return a;
}
#define MBAR_INIT(a, c) asm volatile("mbarrier.init.shared.b64 [%0], %1;" :: "r"(a), "r"(c) : "memory")
#define MBAR_INVAL(a)   asm volatile("mbarrier.inval.shared.b64 [%0];" :: "r"(a) : "memory")
#define MBAR_WAIT(a, ph) do { \
    uint32_t _m = (a), _p = (ph), _d; \
    asm volatile("{ .reg .pred p; mbarrier.try_wait.parity.acquire.cta.shared::cta.b64 p, [%1], %2; selp.b32 %0, 1, 0, p; }" \
        : "=r"(_d) : "r"(_m), "r"(_p) : "memory"); \
    if (!_d) { \
        asm volatile("{ .reg .pred P1; WL%=: mbarrier.try_wait.parity.acquire.cta.shared::cta.b64 P1, [%0], %1, 0x989680; @P1 bra.uni WD%=; bra.uni WL%=; WD%=: }" \
            :: "r"(_m), "r"(_p) : "memory"); \
    } } while (0)

#if defined(__CUDA_ARCH_FEAT_SM103_ALL)
__device__ __forceinline__ uint32_t elect_one() {
    uint32_t p;
    asm volatile("{ .reg .pred p; elect.sync _|p, 0xFFFFFFFF; selp.b32 %0, 1, 0, p; }" : "=r"(p));
    return p;
}
#define TC_ALLOC(sa, n)  asm volatile("tcgen05.alloc.cta_group::1.sync.aligned.shared::cta.b32 [%0], %1;" :: "r"(sa), "r"(n) : "memory")
#define TC_DEALLOC(t, n) asm volatile("tcgen05.dealloc.cta_group::1.sync.aligned.b32 %0, %1;" :: "r"(t), "r"(n))
#define TC_COMMIT(a)     asm volatile("tcgen05.commit.cta_group::1.mbarrier::arrive::one.shared::cluster.b64 [%0];" :: "r"(a) : "memory")
#define TC_FENCE_AFTER() asm volatile("tcgen05.fence::after_thread_sync;" ::: "memory")
#define TC_FENCE_BEFORE() asm volatile("tcgen05.fence::before_thread_sync;" ::: "memory")
#define TC_WAIT_LD()     asm volatile("tcgen05.wait::ld.sync.aligned;" ::: "memory")
#define FENCE_ASYNC()    asm volatile("fence.proxy.async.shared::cta;" ::: "memory")

#define TC_LD_X32(r, ta) \
    asm volatile("tcgen05.ld.sync.aligned.32x32b.x32.b32 " \
        "{%0,%1,%2,%3,%4,%5,%6,%7,%8,%9,%10,%11,%12,%13,%14,%15," \
        "%16,%17,%18,%19,%20,%21,%22,%23,%24,%25,%26,%27,%28,%29,%30,%31}, [%32];" \
        : "=r"((r)[0]),"=r"((r)[1]),"=r"((r)[2]),"=r"((r)[3]),"=r"((r)[4]),"=r"((r)[5]),"=r"((r)[6]),"=r"((r)[7]), \
          "=r"((r)[8]),"=r"((r)[9]),"=r"((r)[10]),"=r"((r)[11]),"=r"((r)[12]),"=r"((r)[13]),"=r"((r)[14]),"=r"((r)[15]), \
          "=r"((r)[16]),"=r"((r)[17]),"=r"((r)[18]),"=r"((r)[19]),"=r"((r)[20]),"=r"((r)[21]),"=r"((r)[22]),"=r"((r)[23]), \
          "=r"((r)[24]),"=r"((r)[25]),"=r"((r)[26]),"=r"((r)[27]),"=r"((r)[28]),"=r"((r)[29]),"=r"((r)[30]),"=r"((r)[31]) \
        : "r"(ta))

// SMEM descriptor: SW128, version=1 (Blackwell), SBO=64, LBO=1 (canonical K-major 128B rows)
static __device__ __forceinline__ uint64_t make_desc(uint32_t addr) {
    const uint64_t base = (uint64_t(2) << 61) | (uint64_t(1) << 46) | (uint64_t(64) << 32) | (uint64_t(1) << 16);
    return base | ((uint64_t)(addr >> 4) & 0x3FFF);
}

// cg1 SS bf16 MMA: D[M=128,N=128] fp32 += A[128,16] * B[128,16]^T
#define GEMM_IDESC 0x08200490u
__device__ __forceinline__ void mma_f16_ss(uint32_t d, uint64_t ad, uint64_t bd, uint32_t en) {
    asm volatile(
        "{ .reg .pred p; setp.ne.u32 p, %5, 0;\n\t"
        "tcgen05.mma.cta_group::1.kind::f16 [%0], %1, %2, %3, {%4, %4, %4, %4}, p; }"
        :: "r"(d), "l"(ad), "l"(bd), "r"(GEMM_IDESC), "r"(0u), "r"(en)
        : "memory");
}
#endif  // __CUDA_ARCH_FEAT_SM103_ALL

// canonical SW128 byte offset within a 128row x 128byte tile
__device__ __forceinline__ uint32_t tile_off(int row, int i16 /*16B chunk 0..7*/) {
    uint32_t byte = (uint32_t)row * 128u + (uint32_t)i16 * 16u;
    return byte ^ ((byte >> 3) & 0x70);
}

// ---------------- dtype detection ----------------
__global__ void k_detect(const int* __restrict__ ei32) {
    int mode = 1;
    for (int i = 0; i < 64; ++i) {
        if (ei32[2 * i + 1] != 0) { mode = 0; break; }
    }
    g_i64 = mode;
}

__device__ __forceinline__ int idx_at(const int* p32, int i) {
    return g_i64 ? p32[2 * i] : p32[i];
}

// ---------------- CSR build ----------------
__global__ void k_zero_deg() {
    int i = blockIdx.x * blockDim.x + threadIdx.x;
    if (i < NN) g_deg[i] = 0;
}

__global__ void k_count(const int* __restrict__ ei32) {
    int e = blockIdx.x * blockDim.x + threadIdx.x;
    if (e < NE) atomicAdd(&g_deg[idx_at(ei32, NE + e)], 1);
}

__global__ void k_partial() {
    __shared__ int sh[SCAN_B];
    int idx = blockIdx.x * SCAN_B + threadIdx.x;
    int v = (idx < NN) ? g_deg[idx] : 0;
    sh[threadIdx.x] = v;
    __syncthreads();
    for (int off = SCAN_B / 2; off > 0; off >>= 1) {
        if (threadIdx.x < off) sh[threadIdx.x] += sh[threadIdx.x + off];
        __syncthreads();
    }
    if (threadIdx.x == 0) g_part[blockIdx.x] = sh[0];
}

__global__ void k_scanpart() {
    __shared__ int sh[SCAN_B];
    int t = threadIdx.x;
    int v = (t < NBLK) ? g_part[t] : 0;
    sh[t] = v;
    __syncthreads();
    for (int off = 1; off < SCAN_B; off <<= 1) {
        int u = (t >= off) ? sh[t - off] : 0;
        __syncthreads();
        sh[t] += u;
        __syncthreads();
    }
    if (t < NBLK) g_poff[t] = sh[t] - v;
}

__global__ void k_offsets() {
    __shared__ int sh[SCAN_B];
    int t = threadIdx.x;
    int idx = blockIdx.x * SCAN_B + t;
    int d = (idx < NN) ? g_deg[idx] : 0;
    sh[t] = d;
    __syncthreads();
    for (int off = 1; off < SCAN_B; off <<= 1) {
        int u = (t >= off) ? sh[t - off] : 0;
        __syncthreads();
        sh[t] += u;
        __syncthreads();
    }
    if (idx < NN) {
        int o = g_poff[blockIdx.x] + sh[t] - d;
        g_off[idx] = o;
        g_cur[idx] = o;
        if (idx == NN - 1) g_off[NN] = o + d;
    }
}

__global__ void k_fill(const int* __restrict__ ei32) {
    int e = blockIdx.x * blockDim.x + threadIdx.x;
    if (e < NE) {
        int d = idx_at(ei32, NE + e);
        int s = idx_at(ei32, e);
        int pos = atomicAdd(&g_cur[d], 1);
        g_csr[pos] = s;
    }
}

// ---------------- weight prep: Wt hi/lo [4][128 n][256 k] ----------------
__global__ void k_wprep(const float* __restrict__ w0, const float* __restrict__ w1,
                        const float* __restrict__ w2, const float* __restrict__ w3) {
    int idx = blockIdx.x * blockDim.x + threadIdx.x;
    if (idx >= 4 * 128 * 256) return;
    int s = idx >> 15;
    int rem = idx & 32767;
    int n = rem >> 8;
    int k = rem & 255;
    const float* w = s == 0 ? w0 : s == 1 ? w1 : s == 2 ? w2 : w3;
    float v = w[(size_t)k * 128 + n];
    __nv_bfloat16 hi, lo;
    split_bf16(v, hi, lo);
    ((__nv_bfloat16*)g_Bhi4)[idx] = hi;
    ((__nv_bfloat16*)g_Blo4)[idx] = lo;
}

// ---------------- x -> A hi/lo (cols 0..127) ----------------
__global__ void k_conv0(const float* __restrict__ x) {
    int idx = blockIdx.x * blockDim.x + threadIdx.x;  // NN*32
    if (idx >= NN * 32) return;
    int gr = idx >> 5;
    int cg = (idx & 31) * 4;
    float4 v = *(const float4*)(x + (size_t)gr * DD + cg);
    __nv_bfloat16 h0, h1, h2, h3, l0, l1, l2, l3;
    split_bf16(v.x, h0, l0); split_bf16(v.y, h1, l1);
    split_bf16(v.z, h2, l2); split_bf16(v.w, h3, l3);
    unsigned* hp = (unsigned*)g_Ahi4 + (size_t)gr * 128 + cg / 2;
    unsigned* lp = (unsigned*)g_Alo4 + (size_t)gr * 128 + cg / 2;
    hp[0] = pack_bf2(h0, h1); hp[1] = pack_bf2(h2, h3);
    lp[0] = pack_bf2(l0, l1); lp[1] = pack_bf2(l2, l3);
}

// ---------------- aggregation: warp-per-node gather-max -> A hi/lo cols 128..255 ----------------
__global__ void k_agg(int insel, const float* __restrict__ x, const float* __restrict__ doutc) {
    const float* h = sel_in(insel, x, doutc);
    const int warp = (blockIdx.x * blockDim.x + threadIdx.x) >> 5;
    const int lane = threadIdx.x & 31;
    if (warp >= NN) return;
    const int e0 = g_off[warp];
    const int e1 = g_off[warp + 1];
    float4 m = make_float4(0.f, 0.f, 0.f, 0.f);
    if (e1 > e0) {
        const float ni = __uint_as_float(NEG_INF_BITS);
        m = make_float4(ni, ni, ni, ni);
        int e = e0;
        for (; e + 3 < e1; e += 4) {
            int s0 = g_csr[e], s1 = g_csr[e + 1], s2 = g_csr[e + 2], s3 = g_csr[e + 3];
            float4 v0 = ((const float4*)h)[(size_t)s0 * 32 + lane];
            float4 v1 = ((const float4*)h)[(size_t)s1 * 32 + lane];
            float4 v2 = ((const float4*)h)[(size_t)s2 * 32 + lane];
            float4 v3 = ((const float4*)h)[(size_t)s3 * 32 + lane];
            m.x = fmaxf(fmaxf(m.x, v0.x), fmaxf(v1.x, fmaxf(v2.x, v3.x)));
            m.y = fmaxf(fmaxf(m.y, v0.y), fmaxf(v1.y, fmaxf(v2.y, v3.y)));
            m.z = fmaxf(fmaxf(m.z, v0.z), fmaxf(v1.z, fmaxf(v2.z, v3.z)));
            m.w = fmaxf(fmaxf(m.w, v0.w), fmaxf(v1.w, fmaxf(v2.w, v3.w)));
        }
        for (; e < e1; ++e) {
            int s0 = g_csr[e];
            float4 v0 = ((const float4*)h)[(size_t)s0 * 32 + lane];
            m.x = fmaxf(m.x, v0.x); m.y = fmaxf(m.y, v0.y);
            m.z = fmaxf(m.z, v0.z); m.w = fmaxf(m.w, v0.w);
        }
    }
    __nv_bfloat16 h0, h1, h2, h3, l0, l1, l2, l3;
    split_bf16(m.x, h0, l0); split_bf16(m.y, h1, l1);
    split_bf16(m.z, h2, l2); split_bf16(m.w, h3, l3);
    unsigned* hp = (unsigned*)g_Ahi4 + (size_t)warp * 128 + 64 + lane * 2;
    unsigned* lp = (unsigned*)g_Alo4 + (size_t)warp * 128 + 64 + lane * 2;
    hp[0] = pack_bf2(h0, h1); hp[1] = pack_bf2(h2, h3);
    lp[0] = pack_bf2(l0, l1); lp[1] = pack_bf2(l2, l3);
}

// ---------------- persistent tcgen05 GEMM, resident B, TMEM D ping-pong ----------------
// grid=148. B (weights, all 4 chunks hi+lo = 128KB) loaded ONCE per CTA; A double-buffered.
#define S_TMEM 0
#define S_MBAR0 8
#define S_MBAR1 16
#define S_BIAS 64
#define S_A 1024
#define A_SET_BYTES 32768     // Ahi 16KB + Alo 16KB
#define A_T_ALO 16384
#define S_B (S_A + 2 * A_SET_BYTES)        // 66560
#define B_CHUNK_BYTES 32768   // Bhi 16KB + Blo 16KB
#define B_T_BLO 16384
#define S_TOTAL (S_B + 4 * B_CHUNK_BYTES)  // 197632

__global__ void __launch_bounds__(256)
k_gemm_tc(int insel, int outsel, const float* __restrict__ x, float* __restrict__ dout,
          int step, const float* __restrict__ b, int addskip, int writeconv) {
    extern __shared__ char smem[];
    const float* h = sel_in(insel, x, dout);
    float* out = sel_out(outsel, dout);
    const int tid = threadIdx.x;
    const int wid = tid >> 5;
    const int lane = tid & 31;

#if defined(__CUDA_ARCH_FEAT_SM103_ALL)
    const uint32_t sb = smem_u32(smem);
    if (wid == 0) TC_ALLOC(sb + S_TMEM, 256);
    if (tid == 0) { MBAR_INIT(sb + S_MBAR0, 1); MBAR_INIT(sb + S_MBAR1, 1); }
    if (tid < 32) ((float4*)(smem + S_BIAS))[tid] = ((const float4*)b)[tid];
    __syncthreads();
    uint32_t tmem;
    asm volatile("ld.shared.b32 %0, [%1];" : "=r"(tmem) : "r"(sb + S_TMEM));

    const size_t boff = (size_t)step * 4096;  // uint4 stride per step
    const int lrow = tid >> 1;
    const int lhalf = (tid & 1) * 4;   // i16 base 0 or 4

    // ---- load B (all 4 chunks, hi+lo) once into resident smem ----
    {
#pragma unroll
        for (int c = 0; c < 4; ++c) {
            const uint4* bh = g_Bhi4 + boff + (size_t)lrow * 32 + (size_t)c * 8 + lhalf;
            const uint4* bl = g_Blo4 + boff + (size_t)lrow * 32 + (size_t)c * 8 + lhalf;
            char* base = smem + S_B + c * B_CHUNK_BYTES;
#pragma unroll
            for (int i = 0; i < 4; ++i) {
                uint32_t so = tile_off(lrow, lhalf + i);
                *(uint4*)(base + so) = bh[i];
                *(uint4*)(base + B_T_BLO + so) = bl[i];
            }
        }
        FENCE_ASYNC();
        __syncthreads();
    }

    auto load_chunk = [&](int m0, int c, int set) {
        const uint4 z4 = make_uint4(0, 0, 0, 0);
        const int gr = m0 + lrow;
        const bool valid = gr < NN;
        const uint4* ah = g_Ahi4 + (size_t)gr * 32 + (size_t)c * 8 + lhalf;
        const uint4* al = g_Alo4 + (size_t)gr * 32 + (size_t)c * 8 + lhalf;
        char* base = smem + S_A + set * A_SET_BYTES;
#pragma unroll
        for (int i = 0; i < 4; ++i) {
            uint32_t so = tile_off(lrow, lhalf + i);
            *(uint4*)(base + so) = valid ? ah[i] : z4;
            *(uint4*)(base + A_T_ALO + so) = valid ? al[i] : z4;
        }
    };

    auto issue_chunk = [&](uint32_t dtm, int c, int set) {
        if (wid == 0 && elect_one()) {
            uint32_t abuf = sb + S_A + set * A_SET_BYTES;
            uint32_t bbuf = sb + S_B + c * B_CHUNK_BYTES;
            uint64_t dah = make_desc(abuf);
            uint64_t dal = make_desc(abuf + A_T_ALO);
            uint64_t dbh = make_desc(bbuf);
            uint64_t dbl = make_desc(bbuf + B_T_BLO);
#pragma unroll
            for (int ks = 0; ks < 4; ++ks) {
                uint64_t off = (uint64_t)(ks * 2);
                mma_f16_ss(dtm, dah + off, dbh + off, (c == 0 && ks == 0) ? 0u : 1u);
            }
#pragma unroll
            for (int ks = 0; ks < 4; ++ks) {
                uint64_t off = (uint64_t)(ks * 2);
                mma_f16_ss(dtm, dah + off, dbl + off, 1u);
            }
#pragma unroll
            for (int ks = 0; ks < 4; ++ks) {
                uint64_t off = (uint64_t)(ks * 2);
                mma_f16_ss(dtm, dal + off, dbh + off, 1u);
            }
            TC_COMMIT(sb + S_MBAR0 + set * 8);
        }
    };

    const float* bias = (const float*)(smem + S_BIAS);
    auto epilogue = [&](int m0, uint32_t dtm) {
        const int egr = m0 + (wid & 3) * 32 + lane;
        const int colbase = (wid >> 2) * 64;
        uint32_t r[64];
        TC_LD_X32(r, dtm + colbase);
        TC_LD_X32(r + 32, dtm + colbase + 32);
        TC_WAIT_LD();
        if (egr < NN) {
#pragma unroll
            for (int cq = 0; cq < 64; cq += 32) {
                const int cb = colbase + cq;
                const uint32_t* rr = r + cq;
                const float* hr = h + (size_t)egr * DD + cb;
                float* orow = out + (size_t)egr * DD + cb;
                unsigned* hp = (unsigned*)g_Ahi4 + (size_t)egr * 128 + cb / 2;
                unsigned* lp = (unsigned*)g_Alo4 + (size_t)egr * 128 + cb / 2;
#pragma unroll
                for (int c0 = 0; c0 < 32; c0 += 4) {
                    float4 v;
                    v.x = __uint_as_float(rr[c0 + 0]) + bias[cb + c0 + 0];
                    v.y = __uint_as_float(rr[c0 + 1]) + bias[cb + c0 + 1];
                    v.z = __uint_as_float(rr[c0 + 2]) + bias[cb + c0 + 2];
                    v.w = __uint_as_float(rr[c0 + 3]) + bias[cb + c0 + 3];
                    v.x = v.x > 0.f ? v.x : 0.01f * v.x;
                    v.y = v.y > 0.f ? v.y : 0.01f * v.y;
                    v.z = v.z > 0.f ? v.z : 0.01f * v.z;
                    v.w = v.w > 0.f ? v.w : 0.01f * v.w;
                    if (addskip) {
                        float4 hv = *(const float4*)(hr + c0);
                        v.x += hv.x; v.y += hv.y; v.z += hv.z; v.w += hv.w;
                    }
                    *(float4*)(orow + c0) = v;
                    if (writeconv) {
                        __nv_bfloat16 h0, h1, h2, h3, l0, l1, l2, l3;
                        split_bf16(v.x, h0, l0); split_bf16(v.y, h1, l1);
                        split_bf16(v.z, h2, l2); split_bf16(v.w, h3, l3);
                        hp[c0 / 2 + 0] = pack_bf2(h0, h1); hp[c0 / 2 + 1] = pack_bf2(h2, h3);
                        lp[c0 / 2 + 0] = pack_bf2(l0, l1); lp[c0 / 2 + 1] = pack_bf2(l2, l3);
                    }
                }
            }
        }
    };

    int w0 = 0, w1 = 0;
    int iter = 0;
    int prev_m0 = -1;
    for (int tile = blockIdx.x; tile < NTILES; tile += GEMM_GRID) {
        const int m0 = tile * 128;
        const uint32_t dcur = tmem + (iter & 1) * 128;
        const uint32_t dprev = tmem + ((iter ^ 1) & 1) * 128;

        if (iter > 0) { MBAR_WAIT(sb + S_MBAR0, w0 & 1); ++w0; }
        __syncthreads();
        load_chunk(m0, 0, 0);
        FENCE_ASYNC();
        __syncthreads();
        issue_chunk(dcur, 0, 0);

        if (iter > 0) { MBAR_WAIT(sb + S_MBAR1, w1 & 1); ++w1; }
        __syncthreads();
        load_chunk(m0, 1, 1);
        FENCE_ASYNC();
        __syncthreads();
        issue_chunk(dcur, 1, 1);

        MBAR_WAIT(sb + S_MBAR0, w0 & 1); ++w0;
        __syncthreads();
        load_chunk(m0, 2, 0);
        FENCE_ASYNC();
        __syncthreads();
        issue_chunk(dcur, 2, 0);

        if (iter > 0) {
            TC_FENCE_AFTER();
            epilogue(prev_m0, dprev);
        }

        MBAR_WAIT(sb + S_MBAR1, w1 & 1); ++w1;
        __syncthreads();
        load_chunk(m0, 3, 1);
        FENCE_ASYNC();
        __syncthreads();
        issue_chunk(dcur, 3, 1);

        prev_m0 = m0;
        ++iter;
    }
    if (iter > 0) {
        MBAR_WAIT(sb + S_MBAR1, w1 & 1); ++w1;
        TC_FENCE_AFTER();
        __syncthreads();
        epilogue(prev_m0, tmem + ((iter - 1) & 1) * 128);
    }
    TC_FENCE_BEFORE();
    __syncthreads();
    if (wid == 0) {
        if (elect_one()) { MBAR_INVAL(sb + S_MBAR0); MBAR_INVAL(sb + S_MBAR1); }
        TC_DEALLOC(tmem, 256);
    }
#else
    // Correct scalar fallback (only used if the generic compute_103 PTX is JIT'd).
    if (tid < 32) ((float4*)(smem + S_BIAS))[tid] = ((const float4*)b)[tid];
    __syncthreads();
    const float* bias = (const float*)(smem + S_BIAS);
    for (int tile = blockIdx.x; tile < NTILES; tile += GEMM_GRID) {
        const int m0 = tile * 128;
        const int egr = m0 + (wid & 3) * 32 + lane;
        const int colbase = (wid >> 2) * 64;
        if (egr < NN) {
            const __nv_bfloat16* ah = (const __nv_bfloat16*)g_Ahi4 + (size_t)egr * 256;
            const __nv_bfloat16* al = (const __nv_bfloat16*)g_Alo4 + (size_t)egr * 256;
            const __nv_bfloat16* BH = (const __nv_bfloat16*)g_Bhi4 + (size_t)step * 128 * 256;
            const __nv_bfloat16* BL = (const __nv_bfloat16*)g_Blo4 + (size_t)step * 128 * 256;
            for (int cq = 0; cq < 64; cq += 4) {
                int cb = colbase + cq;
                float acc[4] = {0.f, 0.f, 0.f, 0.f};
                for (int k = 0; k < 256; ++k) {
                    float ahv = __bfloat162float(ah[k]);
                    float alv = __bfloat162float(al[k]);
#pragma unroll
                    for (int j = 0; j < 4; ++j) {
                        float bh = __bfloat162float(BH[(size_t)(cb + j) * 256 + k]);
                        float bl = __bfloat162float(BL[(size_t)(cb + j) * 256 + k]);
                        acc[j] += ahv * bh + ahv * bl + alv * bh;
                    }
                }
                const float* hr = h + (size_t)egr * DD;
                float* orow = out + (size_t)egr * DD;
                unsigned* hp = (unsigned*)g_Ahi4 + (size_t)egr * 128;
                unsigned* lp = (unsigned*)g_Alo4 + (size_t)egr * 128;
#pragma unroll
                for (int j = 0; j < 4; j += 2) {
                    float v0 = acc[j] + bias[cb + j];
                    float v1 = acc[j + 1] + bias[cb + j + 1];
                    v0 = v0 > 0.f ? v0 : 0.01f * v0;
                    v1 = v1 > 0.f ? v1 : 0.01f * v1;
                    if (addskip) { v0 += hr[cb + j]; v1 += hr[cb + j + 1]; }
                    orow[cb + j] = v0;
                    orow[cb + j + 1] = v1;
                    if (writeconv) {
                        __nv_bfloat16 h0, h1, l0, l1;
                        split_bf16(v0, h0, l0); split_bf16(v1, h1, l1);
                        hp[(cb + j) / 2] = pack_bf2(h0, h1);
                        lp[(cb + j) / 2] = pack_bf2(l0, l1);
                    }
                }
            }
        }
    }
#endif
}

// ---------------- global pool ----------------
__global__ void k_init_xg() {
    unsigned int i = blockIdx.x * blockDim.x + threadIdx.x;
    if (i < NG * DD) ((unsigned int*)g_xg)[i] = NEG_INF_BITS;
}

__device__ __forceinline__ int lower_bound_b(const int* b32, int n, int v) {
    int lo = 0, hi = n;
    while (lo < hi) {
        int mid = (lo + hi) >> 1;
        if (idx_at(b32, mid) < v) lo = mid + 1;
        else hi = mid;
    }
    return lo;
}

__global__ void k_segmax(const float* __restrict__ h, const int* __restrict__ batch32) {
    const int g = blockIdx.x;
    const int chunk = blockIdx.y;
    const int d = threadIdx.x;
    int start = lower_bound_b(batch32, NN, g);
    int end = lower_bound_b(batch32, NN, g + 1);
    int len = end - start;
    if (len <= 0) return;
    int per = (len + gridDim.y - 1) / gridDim.y;
    int s = start + chunk * per;
    int e = s + per;
    if (e > end) e = end;
    if (s >= e) return;
    float m = __uint_as_float(NEG_INF_BITS);
    for (int r = s; r < e; ++r) m = fmaxf(m, h[(size_t)r * DD + d]);
    atomicMaxF(&g_xg[g * DD + d], m);
}

__global__ void k_combine(float* __restrict__ dout, const float* __restrict__ wg,
                          const float* __restrict__ bg, int out_size) {
    const int g = blockIdx.x;
    const int n = threadIdx.x;
    float acc = bg[n];
    for (int k = 0; k < DD; ++k) {
        float xv = fixneg(g_xg[g * DD + k]);
        acc = fmaf(xv, wg[(size_t)k * DD + n], acc);
    }
    acc = acc > 0.f ? acc : 0.01f * acc;
    long long oi = (long long)NN * DD + g * DD + n;
    if (oi < (long long)out_size) dout[oi] = acc;
}

// ---------------- launch ----------------
extern "C" void kernel_launch(void* const* d_in, const int* in_sizes, int n_in,
                              void* d_out, int out_size) {
    const float* x = (const float*)d_in[0];
    const int* ei32 = (const int*)d_in[1];
    const int* batch32 = (const int*)d_in[2];
    const int wb = n_in - 10;  // w0,b0,w1,b1,w2,b2,w3,b3,wg,bg
    float* dout = (float*)d_out;

    static int smem_set = 0;
    if (!smem_set) {
        cudaFuncSetAttribute(k_gemm_tc, cudaFuncAttributeMaxDynamicSharedMemorySize, S_TOTAL);
        smem_set = 1;
    }

    k_detect<<<1, 1>>>(ei32);

    // CSR build
    k_zero_deg<<<(NN + 255) / 256, 256>>>();
    k_count<<<(NE + 255) / 256, 256>>>(ei32);
    k_partial<<<NBLK, SCAN_B>>>();
    k_scanpart<<<1, SCAN_B>>>();
    k_offsets<<<NBLK, SCAN_B>>>();
    k_fill<<<(NE + 255) / 256, 256>>>(ei32);

    // weight + input conversion
    k_wprep<<<(4 * 128 * 256 + 255) / 256, 256>>>(
        (const float*)d_in[wb + 0], (const float*)d_in[wb + 2],
        (const float*)d_in[wb + 4], (const float*)d_in[wb + 6]);
    k_conv0<<<(NN * 32 + 255) / 256, 256>>>(x);

    int insel = 0;
    for (int s = 0; s < 4; ++s) {
        int outsel = (s == 3) ? 3 : ((s % 2 == 0) ? 1 : 2);
        k_agg<<<(NN * 32 + 255) / 256, 256>>>(insel, x, dout);
        k_gemm_tc<<<GEMM_GRID, 256, S_TOTAL>>>(insel, outsel, x, dout, s,
                                               (const float*)d_in[wb + 2 * s + 1],
                                               s > 0 ? 1 : 0, s < 3 ? 1 : 0);
        insel = outsel;
    }

    k_init_xg<<<8, 256>>>();
    dim3 gsg(NG, 32);
    k_segmax<<<gsg, 128>>>(dout, batch32);
    k_combine<<<NG, 128>>>(dout, (const float*)d_in[wb + 8], (const float*)d_in[wb + 9], out_size);
}